// round 1
// baseline (speedup 1.0000x reference)
#include <cuda_runtime.h>

// GVCNN group pooling, collapsed to a single weighted view-sum per sample.
//
// out[n,c] = sum_v coef[n, gid[n,v]] * RPs[n,v,c]
//   y[n,v]      = dot(RPs[n,v,:], w) + b
//   score       = x/(1+x), x = |y| + eps          (== sigmoid(log(|y|+eps)))
//   gid         = min(int(score*10), 9) >> 1      (bins 0..4)
//   gsize[g]    = #views in bin g
//   gscore[g]   = sum_{v in g} ceil(score_v * gsize[g]) / (gsize[g]+eps)
//   coef[g]     = gscore[g] / ((gsize[g]+eps) * (sum_g gscore + eps))
//
// One block (256 threads) per n. Thread c holds RPs[n, 0..11, c] in registers,
// reused for both the dot-product reduction and the final weighted sum:
// RPs is read from HBM exactly once.

#define NV 12
#define NC 256
#define NBINS 5
#define EPSF 1e-6f

__global__ __launch_bounds__(NC) void gvcnn_kernel(
    const float* __restrict__ RPs,
    const float* __restrict__ w,
    const float* __restrict__ b,
    float* __restrict__ out)
{
    const int n    = blockIdx.x;
    const int c    = threadIdx.x;          // channel 0..255
    const int lane = c & 31;
    const int warp = c >> 5;               // 0..7

    // ---- load this thread's 12 view values (coalesced, MLP=12) ----
    const float* base = RPs + ((size_t)n * NV) * NC + c;
    float r[NV];
#pragma unroll
    for (int v = 0; v < NV; v++) r[v] = base[v * NC];

    const float wc = __ldg(&w[c]);

    // ---- 12 simultaneous block reductions: y[v] = sum_c r[v]*w[c] ----
    float p[NV];
#pragma unroll
    for (int v = 0; v < NV; v++) p[v] = r[v] * wc;

#pragma unroll
    for (int off = 16; off > 0; off >>= 1) {
#pragma unroll
        for (int v = 0; v < NV; v++)
            p[v] += __shfl_down_sync(0xffffffffu, p[v], off);
    }

    __shared__ float wpart[8][NV];
    __shared__ float s_score[NV];
    __shared__ int   s_gid[NV];
    __shared__ float s_coef[NV];

    if (lane == 0) {
#pragma unroll
        for (int v = 0; v < NV; v++) wpart[warp][v] = p[v];
    }
    __syncthreads();

    // ---- 12 threads finish the cross-warp sum + score/bin ----
    if (c < NV) {
        float y = b[0];
#pragma unroll
        for (int wi = 0; wi < 8; wi++) y += wpart[wi][c];
        const float x = fabsf(y) + EPSF;
        const float s = x / (1.0f + x);               // == sigmoid(log(x))
        s_score[c] = s;
        s_gid[c]   = min((int)(s * 10.0f), 9) >> 1;   // 0..4
    }
    __syncthreads();

    // ---- single thread runs the tiny serial binning logic ----
    if (c == 0) {
        float gsize[NBINS]  = {0.f, 0.f, 0.f, 0.f, 0.f};
        float gscore[NBINS] = {0.f, 0.f, 0.f, 0.f, 0.f};
#pragma unroll
        for (int v = 0; v < NV; v++) gsize[s_gid[v]] += 1.0f;
#pragma unroll
        for (int v = 0; v < NV; v++) {
            const int g = s_gid[v];
            gscore[g] += ceilf(s_score[v] * gsize[g]);
        }
        float total = 0.f;
#pragma unroll
        for (int g = 0; g < NBINS; g++) {
            gscore[g] /= (gsize[g] + EPSF);   // now == reference group_score
            total     += gscore[g];
        }
        const float inv_total = 1.0f / (total + EPSF);
#pragma unroll
        for (int v = 0; v < NV; v++) {
            const int g = s_gid[v];
            s_coef[v] = gscore[g] / (gsize[g] + EPSF) * inv_total;
        }
    }
    __syncthreads();

    // ---- final weighted sum straight from registers ----
    float acc = 0.f;
#pragma unroll
    for (int v = 0; v < NV; v++) acc += s_coef[v] * r[v];
    out[(size_t)n * NC + c] = acc;
}

extern "C" void kernel_launch(void* const* d_in, const int* in_sizes, int n_in,
                              void* d_out, int out_size)
{
    const float* RPs = (const float*)d_in[0];   // [8192, 12, 256] f32
    const float* w   = (const float*)d_in[1];   // [256] f32
    const float* b   = (const float*)d_in[2];   // [1] f32
    float* out       = (float*)d_out;           // [8192, 256] f32

    const int n = in_sizes[0] / (NV * NC);      // 8192
    gvcnn_kernel<<<n, NC>>>(RPs, w, b, out);
}

// round 3
// speedup vs baseline: 2.2231x; 2.2231x over previous
#include <cuda_runtime.h>

// GVCNN group pooling collapsed to out[n,c] = sum_v coef[n,gid[n,v]] * RPs[n,v,c].
//
// One WARP per sample n, no smem, no __syncthreads:
//   - each lane owns 8 channels: float4 chunks {lane, lane+32} of the 64
//     float4s per view -> every LDG.128 / STG.128 is a coalesced 512B access.
//   - 12 view dot-products vs w reduced with shfl_xor butterflies; the
//     butterfly leaves the full sum in EVERY lane, so all lanes redundantly
//     compute the (tiny) binning/coefficient logic: no broadcast needed.
//   - RPs[n] lives in registers (24 x float4) and is read from HBM once,
//     reused for the final weighted sum.

#define NV 12
#define NBINS 5
#define EPSF 1e-6f

__global__ __launch_bounds__(128) void gvcnn_kernel(
    const float4* __restrict__ RPs4,   // [N, 12, 64] float4
    const float4* __restrict__ w4p,    // [64] float4
    const float*  __restrict__ b,
    float4*       __restrict__ out4)   // [N, 64] float4
{
    const int lane = threadIdx.x & 31;
    const int wrp  = threadIdx.x >> 5;                    // 0..3
    const size_t n = (size_t)blockIdx.x * 4 + wrp;        // sample id

    // ---- load the whole sample into registers (24 coalesced LDG.128) ----
    const float4* base = RPs4 + n * (NV * 64) + lane;
    float4 r0[NV], r1[NV];
#pragma unroll
    for (int v = 0; v < NV; v++) {
        r0[v] = base[v * 64];
        r1[v] = base[v * 64 + 32];
    }

    const float4 wa = w4p[lane];
    const float4 wb = w4p[lane + 32];

    // ---- per-view dot partials, then 12 butterfly reductions ----
    float p[NV];
#pragma unroll
    for (int v = 0; v < NV; v++) {
        p[v] = r0[v].x * wa.x + r0[v].y * wa.y + r0[v].z * wa.z + r0[v].w * wa.w
             + r1[v].x * wb.x + r1[v].y * wb.y + r1[v].z * wb.z + r1[v].w * wb.w;
    }
#pragma unroll
    for (int off = 16; off > 0; off >>= 1) {
#pragma unroll
        for (int v = 0; v < NV; v++)
            p[v] += __shfl_xor_sync(0xffffffffu, p[v], off);
    }
    // every lane now holds all 12 full dot products in p[].

    // ---- binning logic, computed redundantly by all lanes (no sync) ----
    const float bb = b[0];
    float score[NV];
    int   gid[NV];
#pragma unroll
    for (int v = 0; v < NV; v++) {
        const float x = fabsf(p[v] + bb) + EPSF;
        const float s = x / (1.0f + x);                 // == sigmoid(log(x))
        score[v] = s;
        gid[v]   = min((int)(s * 10.0f), 9) >> 1;       // 0..4
    }
    float gsize[NBINS]  = {0.f, 0.f, 0.f, 0.f, 0.f};
    float gscore[NBINS] = {0.f, 0.f, 0.f, 0.f, 0.f};
#pragma unroll
    for (int v = 0; v < NV; v++) gsize[gid[v]] += 1.0f;
#pragma unroll
    for (int v = 0; v < NV; v++)
        gscore[gid[v]] += ceilf(score[v] * gsize[gid[v]]);
    float total = 0.f;
#pragma unroll
    for (int g = 0; g < NBINS; g++) {
        gscore[g] /= (gsize[g] + EPSF);                 // reference group_score
        total     += gscore[g];
    }
    const float inv_total = 1.0f / (total + EPSF);

    // ---- final weighted sum straight from the register tile ----
    float4 a0 = make_float4(0.f, 0.f, 0.f, 0.f);
    float4 a1 = make_float4(0.f, 0.f, 0.f, 0.f);
#pragma unroll
    for (int v = 0; v < NV; v++) {
        const int g = gid[v];
        const float cf = gscore[g] / (gsize[g] + EPSF) * inv_total;
        a0.x += cf * r0[v].x;  a0.y += cf * r0[v].y;
        a0.z += cf * r0[v].z;  a0.w += cf * r0[v].w;
        a1.x += cf * r1[v].x;  a1.y += cf * r1[v].y;
        a1.z += cf * r1[v].z;  a1.w += cf * r1[v].w;
    }
    out4[n * 64 + lane]      = a0;
    out4[n * 64 + 32 + lane] = a1;
}

extern "C" void kernel_launch(void* const* d_in, const int* in_sizes, int n_in,
                              void* d_out, int out_size)
{
    const float4* RPs4 = (const float4*)d_in[0];   // [8192,12,256] f32
    const float4* w4p  = (const float4*)d_in[1];   // [256] f32
    const float*  b    = (const float*)d_in[2];    // [1] f32
    float4* out4       = (float4*)d_out;           // [8192,256] f32

    const int n = in_sizes[0] / (NV * 256);        // 8192
    gvcnn_kernel<<<n / 4, 128>>>(RPs4, w4p, b, out4);
}